// round 5
// baseline (speedup 1.0000x reference)
#include <cuda_runtime.h>

// Fused 2-layer MLP:
//   h[b,f]  = relu(sum_i in[b,f,i] * W1[f,i] + b1[f])      (B=8192, F=256, I=128)
//   out[b,o]= relu(sum_f h[b,f]   * W2[o,f] + b2[o])       (O=128)
//
// HBM-streaming bound: 1 GiB input read once. One persistent CTA per SM.
// W1 lives in SMEM (128KB); W2 lives in registers (64/thread); h + partials in SMEM.

#define THREADS 512

constexpr int Bn = 8192;
constexpr int Fn = 256;
constexpr int In = 128;   // floats per (b,f) row  -> 32 float4
constexpr int On = 128;

// SMEM layout (floats):
//  [0,      32768)  W1 as float4[256][32]
//  [32768,  33024)  h[256]
//  [33024,  33536)  partial[4][128]
//  [33536,  33792)  b1[256]
//  [33792,  33920)  b2[128]
constexpr int SM_W1   = 0;
constexpr int SM_H    = 32768;
constexpr int SM_PART = 33024;
constexpr int SM_B1   = 33536;
constexpr int SM_B2   = 33792;
constexpr int SM_FLOATS = 33920;
constexpr int SMEM_BYTES = SM_FLOATS * 4;   // 135,680 B

__global__ __launch_bounds__(THREADS, 1)
void mlp_fused_kernel(const float* __restrict__ in,
                      const float* __restrict__ W1,
                      const float* __restrict__ b1,
                      const float* __restrict__ W2,
                      const float* __restrict__ b2,
                      float* __restrict__ out)
{
    extern __shared__ float smem[];
    float4* w1s4   = reinterpret_cast<float4*>(smem + SM_W1);   // [f][32] float4
    float*  hs     = smem + SM_H;
    float*  part   = smem + SM_PART;
    float*  b1s    = smem + SM_B1;
    float*  b2s    = smem + SM_B2;

    const int tid  = threadIdx.x;
    const int grid = gridDim.x;

    // ---- one-time loads ----
    {
        const float4* W1g = reinterpret_cast<const float4*>(W1);
        #pragma unroll 4
        for (int i = tid; i < Fn * (In / 4); i += THREADS) w1s4[i] = W1g[i];
        for (int i = tid; i < Fn; i += THREADS) b1s[i] = b1[i];
        if (tid < On) b2s[tid] = b2[tid];
    }

    // W2 slice into registers: thread owns output o, f-quarter p (64 f values)
    const int o = tid & 127;
    const int p = tid >> 7;          // 0..3
    float w2r[64];
    {
        const float4* W2g = reinterpret_cast<const float4*>(W2);  // row = 64 float4
        #pragma unroll
        for (int j = 0; j < 16; j++) {
            float4 v = W2g[o * 64 + p * 16 + j];
            w2r[4*j+0] = v.x; w2r[4*j+1] = v.y;
            w2r[4*j+2] = v.z; w2r[4*j+3] = v.w;
        }
    }
    __syncthreads();

    // ---- stage-1 geometry ----
    const int w   = tid >> 5;        // warp 0..15
    const int l   = tid & 31;
    const int sub = l >> 3;          // row within 4-row group (0..3)
    const int c   = l & 7;           // float4 column base (0..7)
    const int rowBase = w * 16;      // 16 feature rows per warp

    const float4* in4 = reinterpret_cast<const float4*>(in);
    const int b0 = blockIdx.x;

    // pipeline staging: 4 float4 = one 4-row group slice per lane
    float4 rs[2][4];

    // prime the pipeline: (b0, group 0)
    {
        int base = (b0 * Fn + rowBase + sub) * 32 + c;
        #pragma unroll
        for (int k = 0; k < 4; k++) rs[0][k] = in4[base + 8 * k];
    }

    for (int b = b0; b < Bn; b += grid) {
        // ---- stage 1: h[f] for this batch ----
        int cur = 0;
        #pragma unroll
        for (int g = 0; g < 4; g++) {
            // prefetch next group (or group 0 of next batch) BEFORE the barrier
            int nb, ng;
            if (g < 3) { nb = b; ng = g + 1; }
            else {
                nb = b + grid; ng = 0;
                if (nb >= Bn) nb = b0;   // harmless dummy, value unused
            }
            {
                int base = (nb * Fn + rowBase + ng * 4 + sub) * 32 + c;
                #pragma unroll
                for (int k = 0; k < 4; k++) rs[cur ^ 1][k] = in4[base + 8 * k];
            }

            // compute current group: row r, lane covers f4-cols c, c+8, c+16, c+24
            const int r = rowBase + g * 4 + sub;
            const float4* wrow = &w1s4[r * 32 + c];
            float a0 = 0.f, a1 = 0.f;
            #pragma unroll
            for (int k = 0; k < 4; k++) {
                float4 x  = rs[cur][k];
                float4 wv = wrow[8 * k];
                a0 = fmaf(x.x, wv.x, a0);
                a1 = fmaf(x.y, wv.y, a1);
                a0 = fmaf(x.z, wv.z, a0);
                a1 = fmaf(x.w, wv.w, a1);
            }
            float s = a0 + a1;
            // reduce across the 8 lanes that share this row
            s += __shfl_xor_sync(0xffffffffu, s, 4);
            s += __shfl_xor_sync(0xffffffffu, s, 2);
            s += __shfl_xor_sync(0xffffffffu, s, 1);
            if (c == 0) hs[r] = fmaxf(s + b1s[r], 0.f);
            cur ^= 1;
        }
        __syncthreads();   // h ready

        // ---- stage 2: partial[p][o] = sum over f in [64p, 64p+64) ----
        {
            const float4* hq = reinterpret_cast<const float4*>(hs + p * 64);
            float acc0 = 0.f, acc1 = 0.f, acc2 = 0.f, acc3 = 0.f;
            #pragma unroll
            for (int j = 0; j < 16; j++) {
                float4 hv = hq[j];     // warp-broadcast LDS (all lanes same addr)
                acc0 = fmaf(hv.x, w2r[4*j+0], acc0);
                acc1 = fmaf(hv.y, w2r[4*j+1], acc1);
                acc2 = fmaf(hv.z, w2r[4*j+2], acc2);
                acc3 = fmaf(hv.w, w2r[4*j+3], acc3);
            }
            part[p * 128 + o] = (acc0 + acc1) + (acc2 + acc3);
        }
        __syncthreads();   // partials ready

        // ---- final combine + relu + coalesced store ----
        if (tid < On) {
            float v = part[tid] + part[128 + tid] + part[256 + tid] +
                      part[384 + tid] + b2s[tid];
            out[b * On + tid] = fmaxf(v, 0.f);
        }
        // no extra barrier needed: next stage-1 writes hs only, and next
        // stage-2 writes to part happen after the next "h ready" barrier,
        // by which time these readers have arrived at it.
    }
}

extern "C" void kernel_launch(void* const* d_in, const int* in_sizes, int n_in,
                              void* d_out, int out_size)
{
    const float* in_ = (const float*)d_in[0];
    const float* W1  = (const float*)d_in[1];
    const float* b1  = (const float*)d_in[2];
    const float* W2  = (const float*)d_in[3];
    const float* b2  = (const float*)d_in[4];
    float* out       = (float*)d_out;

    int nsm = 0;
    if (cudaDeviceGetAttribute(&nsm, cudaDevAttrMultiProcessorCount, 0) != cudaSuccess
        || nsm <= 0) {
        nsm = 148;
    }

    cudaFuncSetAttribute(mlp_fused_kernel,
                         cudaFuncAttributeMaxDynamicSharedMemorySize, SMEM_BYTES);

    mlp_fused_kernel<<<nsm, THREADS, SMEM_BYTES>>>(in_, W1, b1, W2, b2, out);
}

// round 6
// speedup vs baseline: 1.0563x; 1.0563x over previous
#include <cuda_runtime.h>
#include <cuda_pipeline.h>

// Fused 2-layer MLP, HBM-streaming bound (1 GiB input read once).
//   h[b,f]  = relu(sum_i in[b,f,i]*W1[f,i] + b1[f])   B=8192,F=256,I=128
//   out[b,o]= relu(sum_f h[b,f]*W2[o,f] + b2[o])      O=128
//
// R5 -> R6: input now streamed via cp.async.cg into a 2-deep SMEM ring
// (64KB/SM permanently in flight, survives barriers, bypasses L1, zero
// register residency) + 2 batches per barrier pair (half the barriers).

#define THREADS 512
#define DEPTH 2            // cp.async groups in flight (ring slots)

constexpr int Bn = 8192;
constexpr int Fn = 256;
constexpr int On = 128;

// SMEM layout (floats):
constexpr int SM_W1   = 0;                               // 32768 (128KB)
constexpr int SM_RING = 32768;                           // DEPTH*4*512*4 = 16384 (64KB), [slot][k][tid] float4
constexpr int SM_H    = SM_RING + DEPTH * 4 * THREADS * 4;  // 49152, 512 floats (2 batches)
constexpr int SM_PART = SM_H + 512;                      // 49664, 1024 floats (2 batches x 4 x 128)
constexpr int SM_B1   = SM_PART + 1024;                  // 50688
constexpr int SM_B2   = SM_B1 + 256;                     // 50944
constexpr int SM_FLOATS = SM_B2 + 128;                   // 51072
constexpr int SMEM_BYTES = SM_FLOATS * 4;                // 204,288 B

__global__ __launch_bounds__(THREADS, 1)
void mlp_fused_kernel(const float* __restrict__ in,
                      const float* __restrict__ W1,
                      const float* __restrict__ b1,
                      const float* __restrict__ W2,
                      const float* __restrict__ b2,
                      float* __restrict__ out)
{
    extern __shared__ float smem[];
    float4* w1s4   = reinterpret_cast<float4*>(smem + SM_W1);
    float4* ringf4 = reinterpret_cast<float4*>(smem + SM_RING);
    float*  hs     = smem + SM_H;
    float*  part   = smem + SM_PART;
    float*  b1s    = smem + SM_B1;
    float*  b2s    = smem + SM_B2;

    const int tid  = threadIdx.x;
    const int grid = gridDim.x;
    const int b0   = blockIdx.x;

    // stage-1 geometry: warp owns 16 feature rows; 4-row x 8-lane groups
    const int w   = tid >> 5;
    const int l   = tid & 31;
    const int sub = l >> 3;          // row within group (0..3)
    const int c   = l & 7;           // float4 column base (0..7)
    const int rowBase = w * 16;

    const float4* in4 = reinterpret_cast<const float4*>(in);

    // issue one pipeline group (1/4 batch for this thread) via cp.async.cg
    auto issue_group = [&](int sidx) {
        int bi = b0 + (sidx >> 2) * grid;
        if (bi >= Bn) bi = b0;       // clamped dummy past the end (value unused)
        int chunk = sidx & 3;
        int base = (bi * Fn + rowBase + chunk * 4 + sub) * 32 + c;
        float4* dst = ringf4 + (sidx & (DEPTH - 1)) * (4 * THREADS) + tid;
        #pragma unroll
        for (int k = 0; k < 4; k++)
            __pipeline_memcpy_async(dst + k * THREADS, in4 + base + 8 * k, 16);
        __pipeline_commit();
    };

    // prime the ring before anything else so DRAM is busy during setup
    #pragma unroll
    for (int t = 0; t < DEPTH; t++) issue_group(t);

    // ---- one-time loads ----
    {
        const float4* W1g = reinterpret_cast<const float4*>(W1);
        #pragma unroll 4
        for (int i = tid; i < Fn * 32; i += THREADS) w1s4[i] = W1g[i];
        for (int i = tid; i < Fn; i += THREADS) b1s[i] = b1[i];
        if (tid < On) b2s[tid] = b2[tid];
    }

    // W2 slice in registers: thread owns output o, f-quarter p
    const int o = tid & 127;
    const int p = tid >> 7;          // 0..3
    float w2r[64];
    {
        const float4* W2g = reinterpret_cast<const float4*>(W2);
        #pragma unroll
        for (int j = 0; j < 16; j++) {
            float4 v = W2g[o * 64 + p * 16 + j];
            w2r[4*j+0] = v.x; w2r[4*j+1] = v.y;
            w2r[4*j+2] = v.z; w2r[4*j+3] = v.w;
        }
    }
    __syncthreads();

    // consume group sidx, write h into hs[hoff..]
    auto step = [&](int sidx, int hoff) {
        __pipeline_wait_prior(DEPTH - 1);   // group sidx landed
        const float4* src = ringf4 + (sidx & (DEPTH - 1)) * (4 * THREADS) + tid;
        float4 x0 = src[0], x1 = src[THREADS], x2 = src[2*THREADS], x3 = src[3*THREADS];
        issue_group(sidx + DEPTH);          // refill this slot (write lands >> after reads)

        const int r = rowBase + (sidx & 3) * 4 + sub;
        const float4* wrow = &w1s4[r * 32 + c];
        float4 w0 = wrow[0], w1v = wrow[8], w2v = wrow[16], w3 = wrow[24];
        float a0 = 0.f, a1 = 0.f;
        a0 = fmaf(x0.x, w0.x, a0);  a1 = fmaf(x0.y, w0.y, a1);
        a0 = fmaf(x0.z, w0.z, a0);  a1 = fmaf(x0.w, w0.w, a1);
        a0 = fmaf(x1.x, w1v.x, a0); a1 = fmaf(x1.y, w1v.y, a1);
        a0 = fmaf(x1.z, w1v.z, a0); a1 = fmaf(x1.w, w1v.w, a1);
        a0 = fmaf(x2.x, w2v.x, a0); a1 = fmaf(x2.y, w2v.y, a1);
        a0 = fmaf(x2.z, w2v.z, a0); a1 = fmaf(x2.w, w2v.w, a1);
        a0 = fmaf(x3.x, w3.x, a0);  a1 = fmaf(x3.y, w3.y, a1);
        a0 = fmaf(x3.z, w3.z, a0);  a1 = fmaf(x3.w, w3.w, a1);
        float s = a0 + a1;
        s += __shfl_xor_sync(0xffffffffu, s, 4);
        s += __shfl_xor_sync(0xffffffffu, s, 2);
        s += __shfl_xor_sync(0xffffffffu, s, 1);
        if (c == 0) hs[hoff + r] = fmaxf(s + b1s[r], 0.f);
    };

    int s = 0;
    int b = b0;
    while (b < Bn) {
        const int bB = b + grid;
        if (bB < Bn) {
            // ---- two batches per barrier pair ----
            #pragma unroll
            for (int g = 0; g < 8; g++) { step(s, (g & 4) ? 256 : 0); s++; }
            __syncthreads();   // h (both batches) ready

            {
                const float4* hqA = reinterpret_cast<const float4*>(hs + p * 64);
                const float4* hqB = reinterpret_cast<const float4*>(hs + 256 + p * 64);
                float A0=0.f, A1=0.f, B0=0.f, B1=0.f;
                #pragma unroll
                for (int j = 0; j < 16; j++) {
                    float4 ha = hqA[j], hb = hqB[j];   // warp-broadcast LDS
                    A0 = fmaf(ha.x, w2r[4*j+0], A0);
                    A1 = fmaf(ha.y, w2r[4*j+1], A1);
                    A0 = fmaf(ha.z, w2r[4*j+2], A0);
                    A1 = fmaf(ha.w, w2r[4*j+3], A1);
                    B0 = fmaf(hb.x, w2r[4*j+0], B0);
                    B1 = fmaf(hb.y, w2r[4*j+1], B1);
                    B0 = fmaf(hb.z, w2r[4*j+2], B0);
                    B1 = fmaf(hb.w, w2r[4*j+3], B1);
                }
                part[p * 128 + o]       = A0 + A1;
                part[512 + p * 128 + o] = B0 + B1;
            }
            __syncthreads();   // partials ready

            if (tid < 256) {
                const int oo  = tid & 127;
                const int off = (tid & 128) ? 512 : 0;
                const int bb  = (tid & 128) ? bB : b;
                float v = part[off + oo] + part[off + 128 + oo] +
                          part[off + 256 + oo] + part[off + 384 + oo] + b2s[oo];
                out[bb * On + oo] = fmaxf(v, 0.f);
            }
            b += 2 * grid;
        } else {
            // ---- single tail batch ----
            #pragma unroll
            for (int g = 0; g < 4; g++) { step(s, 0); s++; }
            __syncthreads();

            {
                const float4* hq = reinterpret_cast<const float4*>(hs + p * 64);
                float A0=0.f, A1=0.f;
                #pragma unroll
                for (int j = 0; j < 16; j++) {
                    float4 hv = hq[j];
                    A0 = fmaf(hv.x, w2r[4*j+0], A0);
                    A1 = fmaf(hv.y, w2r[4*j+1], A1);
                    A0 = fmaf(hv.z, w2r[4*j+2], A0);
                    A1 = fmaf(hv.w, w2r[4*j+3], A1);
                }
                part[p * 128 + o] = A0 + A1;
            }
            __syncthreads();

            if (tid < On) {
                float v = part[tid] + part[128 + tid] + part[256 + tid] +
                          part[384 + tid] + b2s[tid];
                out[b * On + tid] = fmaxf(v, 0.f);
            }
            b += grid;
        }
    }
    __pipeline_wait_prior(0);   // drain dummy tail groups before exit
}

extern "C" void kernel_launch(void* const* d_in, const int* in_sizes, int n_in,
                              void* d_out, int out_size)
{
    const float* in_ = (const float*)d_in[0];
    const float* W1  = (const float*)d_in[1];
    const float* b1  = (const float*)d_in[2];
    const float* W2  = (const float*)d_in[3];
    const float* b2  = (const float*)d_in[4];
    float* out       = (float*)d_out;

    int nsm = 0;
    if (cudaDeviceGetAttribute(&nsm, cudaDevAttrMultiProcessorCount, 0) != cudaSuccess
        || nsm <= 0) {
        nsm = 148;
    }

    cudaFuncSetAttribute(mlp_fused_kernel,
                         cudaFuncAttributeMaxDynamicSharedMemorySize, SMEM_BYTES);

    mlp_fused_kernel<<<nsm, THREADS, SMEM_BYTES>>>(in_, W1, b1, W2, b2, out);
}